// round 5
// baseline (speedup 1.0000x reference)
#include <cuda_runtime.h>
#include <cstdint>

typedef unsigned long long ull;

#define BATCH 8192
#define SEQT  256
#define HID   32
#define RPW   4                    // batch rows per warp
#define ENC_CTAS (BATCH / RPW)

// scratch: decoder per-row gate preactivations, transposed for coalesced loads
__device__ float g_pre[4][BATCH];

// ---- f32x2 helpers (Blackwell packed fp32) ----
__device__ __forceinline__ void fma2(ull &acc, ull a, ull b) {
    asm("fma.rn.f32x2 %0, %1, %2, %0;" : "+l"(acc) : "l"(a), "l"(b));
}
__device__ __forceinline__ ull pack2(float a, float b) {
    ull r;
    asm("mov.b64 %0, {%1, %2};" : "=l"(r)
        : "r"(__float_as_uint(a)), "r"(__float_as_uint(b)));
    return r;
}
__device__ __forceinline__ float hsum2(ull v) {
    unsigned lo, hi;
    asm("mov.b64 {%0, %1}, %2;" : "=r"(lo), "=r"(hi) : "l"(v));
    return __uint_as_float(lo) + __uint_as_float(hi);
}

// ---- fast activations (EX2/RCP; ~2 ulp, saturate correctly) ----
__device__ __forceinline__ float sigm(float x) {
    return __fdividef(1.0f, 1.0f + __expf(-x));
}
__device__ __forceinline__ float tanhx(float x) {
    return 1.0f - __fdividef(2.0f, __expf(2.0f * x) + 1.0f);
}

// ============================================================================
// Encoder: ONE WARP per CTA, FOUR batch rows per warp. The 128 weight regs
// are shared across rows; each row is an independent recurrence chain (ILP).
// Lane j owns hidden unit j; gate rows i=j, f=32+j, g=64+j, o=96+j.
// No cross-warp sync anywhere on the critical path.
// ============================================================================
__global__ void __launch_bounds__(32, 8) enc_kernel(
    const float* __restrict__ x,      // [B, T]
    const float* __restrict__ eWih,   // [128]
    const float* __restrict__ eWhh,   // [128, 32]
    const float* __restrict__ eBih,   // [128]
    const float* __restrict__ eBhh,   // [128]
    const float* __restrict__ dWih,   // [4, 32]
    const float* __restrict__ dBih,   // [4]
    const float* __restrict__ dBhh)   // [4]
{
    __shared__ float xs[RPW][SEQT];
    __shared__ ull   hb[2][RPW][HID / 2];   // [parity][row][kpair]

    const int lane  = threadIdx.x;
    const int rbase = blockIdx.x * RPW;

    // stage x rows (float4-coalesced)
    #pragma unroll
    for (int r = 0; r < RPW; ++r) {
        const float4* s4 = (const float4*)(x + (size_t)(rbase + r) * SEQT);
        ((float4*)xs[r])[lane]      = s4[lane];
        ((float4*)xs[r])[32 + lane] = s4[32 + lane];
    }

    // per-lane recurrent weights, packed over k-pairs (shared by all rows)
    ull wi[16], wf[16], wg[16], wo[16];
    {
        const ull* ri = (const ull*)(eWhh + (size_t)(      lane) * HID);
        const ull* rf = (const ull*)(eWhh + (size_t)(32  + lane) * HID);
        const ull* rg = (const ull*)(eWhh + (size_t)(64  + lane) * HID);
        const ull* ro = (const ull*)(eWhh + (size_t)(96  + lane) * HID);
        #pragma unroll
        for (int k = 0; k < 16; ++k) {
            wi[k] = ri[k]; wf[k] = rf[k]; wg[k] = rg[k]; wo[k] = ro[k];
        }
    }
    const float bi = eBih[lane]      + eBhh[lane];
    const float bf = eBih[32 + lane] + eBhh[32 + lane];
    const float bg = eBih[64 + lane] + eBhh[64 + lane];
    const float bo = eBih[96 + lane] + eBhh[96 + lane];
    const float vi = eWih[lane];
    const float vf = eWih[32 + lane];
    const float vg = eWih[64 + lane];
    const float vo = eWih[96 + lane];

    #pragma unroll
    for (int r = 0; r < RPW; ++r)
        ((float*)hb[0][r])[lane] = 0.0f;
    __syncwarp();

    float h[RPW], c[RPW];
    #pragma unroll
    for (int r = 0; r < RPW; ++r) { h[r] = 0.0f; c[r] = 0.0f; }

    #pragma unroll 1
    for (int t = 0; t < SEQT; t += 2) {
        #pragma unroll
        for (int p = 0; p < 2; ++p) {
            ull ai[RPW], af[RPW], ag[RPW], ao[RPW];
            #pragma unroll
            for (int r = 0; r < RPW; ++r) {
                const float xv = xs[r][t + p];
                ai[r] = pack2(fmaf(xv, vi, bi), 0.0f);
                af[r] = pack2(fmaf(xv, vf, bf), 0.0f);
                ag[r] = pack2(fmaf(xv, vg, bg), 0.0f);
                ao[r] = pack2(fmaf(xv, vo, bo), 0.0f);
            }

            #pragma unroll
            for (int k = 0; k < 16; ++k) {
                #pragma unroll
                for (int r = 0; r < RPW; ++r) {
                    const ull h2 = hb[p][r][k];      // LDS.64 broadcast
                    fma2(ai[r], wi[k], h2);
                    fma2(af[r], wf[k], h2);
                    fma2(ag[r], wg[k], h2);
                    fma2(ao[r], wo[k], h2);
                }
            }

            #pragma unroll
            for (int r = 0; r < RPW; ++r) {
                const float I = sigm(hsum2(ai[r]));
                const float F = sigm(hsum2(af[r]));
                const float G = tanhx(hsum2(ag[r]));
                const float O = sigm(hsum2(ao[r]));
                c[r] = fmaf(F, c[r], I * G);
                h[r] = O * tanhx(c[r]);
                ((float*)hb[p ^ 1][r])[lane] = h[r];
            }
            __syncwarp();
        }
    }

    // decoder input projection per row: pg = sum_j dWih[g][j]*h[j]
    const float dw0 = dWih[lane];
    const float dw1 = dWih[32 + lane];
    const float dw2 = dWih[64 + lane];
    const float dw3 = dWih[96 + lane];
    #pragma unroll
    for (int r = 0; r < RPW; ++r) {
        float p0 = h[r] * dw0;
        float p1 = h[r] * dw1;
        float p2 = h[r] * dw2;
        float p3 = h[r] * dw3;
        #pragma unroll
        for (int m = 16; m > 0; m >>= 1) {
            p0 += __shfl_xor_sync(0xffffffffu, p0, m);
            p1 += __shfl_xor_sync(0xffffffffu, p1, m);
            p2 += __shfl_xor_sync(0xffffffffu, p2, m);
            p3 += __shfl_xor_sync(0xffffffffu, p3, m);
        }
        if (lane == 0) {
            g_pre[0][rbase + r] = p0 + dBih[0] + dBhh[0];
            g_pre[1][rbase + r] = p1 + dBih[1] + dBhh[1];
            g_pre[2][rbase + r] = p2 + dBih[2] + dBhh[2];
            g_pre[3][rbase + r] = p3 + dBih[3] + dBhh[3];
        }
    }
}

// ============================================================================
// Decoder: one batch row per THREAD (H=1 scalar recurrence). 8192 threads.
// ============================================================================
__global__ void __launch_bounds__(32) dec_kernel(
    const float* __restrict__ dWhh,   // [4]
    float* __restrict__ out)          // [B, T]
{
    const int r = blockIdx.x * 32 + threadIdx.x;

    const float pre0 = g_pre[0][r];
    const float pre1 = g_pre[1][r];
    const float pre2 = g_pre[2][r];
    const float pre3 = g_pre[3][r];
    const float q0 = dWhh[0], q1 = dWhh[1], q2 = dWhh[2], q3 = dWhh[3];

    float hd = 0.0f, cd = 0.0f;
    float* orow = out + (size_t)r * SEQT;

    #pragma unroll 1
    for (int t = 0; t < SEQT; t += 4) {
        float v[4];
        #pragma unroll
        for (int s = 0; s < 4; ++s) {
            const float I = sigm(fmaf(hd, q0, pre0));
            const float F = sigm(fmaf(hd, q1, pre1));
            const float G = tanhx(fmaf(hd, q2, pre2));
            const float O = sigm(fmaf(hd, q3, pre3));
            cd = fmaf(F, cd, I * G);
            hd = O * tanhx(cd);
            v[s] = hd;
        }
        *(float4*)(orow + t) = make_float4(v[0], v[1], v[2], v[3]);
    }
}

extern "C" void kernel_launch(void* const* d_in, const int* in_sizes, int n_in,
                              void* d_out, int out_size) {
    (void)in_sizes; (void)n_in; (void)out_size;
    enc_kernel<<<ENC_CTAS, 32>>>(
        (const float*)d_in[0],
        (const float*)d_in[1], (const float*)d_in[2],
        (const float*)d_in[3], (const float*)d_in[4],
        (const float*)d_in[5],
        (const float*)d_in[7], (const float*)d_in[8]);
    dec_kernel<<<BATCH / 32, 32>>>(
        (const float*)d_in[6],
        (float*)d_out);
}

// round 6
// speedup vs baseline: 1.0695x; 1.0695x over previous
#include <cuda_runtime.h>
#include <cstdint>

typedef unsigned long long ull;

#define BATCH 8192
#define SEQT  256
#define HID   32

// scratch: decoder per-row gate preactivations, transposed for coalesced loads
__device__ float g_pre[4][BATCH];

// ---- f32x2 helpers (Blackwell packed fp32) ----
__device__ __forceinline__ void fma2(ull &acc, ull a, ull b) {
    asm("fma.rn.f32x2 %0, %1, %2, %0;" : "+l"(acc) : "l"(a), "l"(b));
}
__device__ __forceinline__ ull pack2(float a, float b) {
    ull r;
    asm("mov.b64 %0, {%1, %2};" : "=l"(r)
        : "r"(__float_as_uint(a)), "r"(__float_as_uint(b)));
    return r;
}
__device__ __forceinline__ float hsum2(ull v) {
    unsigned lo, hi;
    asm("mov.b64 {%0, %1}, %2;" : "=r"(lo), "=r"(hi) : "l"(v));
    return __uint_as_float(lo) + __uint_as_float(hi);
}

// ---- fast activations (EX2/RCP; ~2 ulp, saturate correctly) ----
__device__ __forceinline__ float sigm(float x) {
    return __fdividef(1.0f, 1.0f + __expf(-x));
}
__device__ __forceinline__ float tanhx(float x) {
    return 1.0f - __fdividef(2.0f, __expf(2.0f * x) + 1.0f);
}

// ============================================================================
// Encoder: ONE WARP per CTA, TWO batch rows per warp (shared weight regs,
// two independent recurrence chains). Lane j owns hidden unit j; gate rows
// i=j, f=32+j, g=64+j, o=96+j. h broadcast via smem ping-pong read as
// 16B vectors (LDS.128). No cross-warp sync on the critical path.
// ============================================================================
__global__ void __launch_bounds__(32, 11) enc_kernel(
    const float* __restrict__ x,      // [B, T]
    const float* __restrict__ eWih,   // [128]
    const float* __restrict__ eWhh,   // [128, 32]
    const float* __restrict__ eBih,   // [128]
    const float* __restrict__ eBhh,   // [128]
    const float* __restrict__ dWih,   // [4, 32]
    const float* __restrict__ dBih,   // [4]
    const float* __restrict__ dBhh)   // [4]
{
    __shared__ float xsA[SEQT], xsB[SEQT];
    __shared__ __align__(16) ull hbA[2][HID / 2], hbB[2][HID / 2];

    const int lane = threadIdx.x;
    const int rA   = blockIdx.x * 2;
    const int rB   = rA + 1;

    // stage both x rows (float4-coalesced)
    {
        const float4* a4 = (const float4*)(x + (size_t)rA * SEQT);
        const float4* b4 = (const float4*)(x + (size_t)rB * SEQT);
        ((float4*)xsA)[lane]      = a4[lane];
        ((float4*)xsA)[32 + lane] = a4[32 + lane];
        ((float4*)xsB)[lane]      = b4[lane];
        ((float4*)xsB)[32 + lane] = b4[32 + lane];
    }

    // per-lane recurrent weights, packed over k-pairs (shared by both rows)
    ull wi[16], wf[16], wg[16], wo[16];
    {
        const ull* ri = (const ull*)(eWhh + (size_t)(      lane) * HID);
        const ull* rf = (const ull*)(eWhh + (size_t)(32  + lane) * HID);
        const ull* rg = (const ull*)(eWhh + (size_t)(64  + lane) * HID);
        const ull* ro = (const ull*)(eWhh + (size_t)(96  + lane) * HID);
        #pragma unroll
        for (int k = 0; k < 16; ++k) {
            wi[k] = ri[k]; wf[k] = rf[k]; wg[k] = rg[k]; wo[k] = ro[k];
        }
    }
    const float bi = eBih[lane]      + eBhh[lane];
    const float bf = eBih[32 + lane] + eBhh[32 + lane];
    const float bg = eBih[64 + lane] + eBhh[64 + lane];
    const float bo = eBih[96 + lane] + eBhh[96 + lane];
    const float vi = eWih[lane];
    const float vf = eWih[32 + lane];
    const float vg = eWih[64 + lane];
    const float vo = eWih[96 + lane];

    ((float*)hbA[0])[lane] = 0.0f;
    ((float*)hbB[0])[lane] = 0.0f;
    __syncwarp();

    float hA = 0.0f, cA = 0.0f;
    float hB = 0.0f, cB = 0.0f;

    #pragma unroll 1
    for (int t = 0; t < SEQT; t += 2) {
        #pragma unroll
        for (int p = 0; p < 2; ++p) {
            const ulonglong2* ra = (const ulonglong2*)hbA[p];
            const ulonglong2* rb = (const ulonglong2*)hbB[p];
            const float xa = xsA[t + p];
            const float xb = xsB[t + p];

            ull aiA = pack2(fmaf(xa, vi, bi), 0.0f);
            ull afA = pack2(fmaf(xa, vf, bf), 0.0f);
            ull agA = pack2(fmaf(xa, vg, bg), 0.0f);
            ull aoA = pack2(fmaf(xa, vo, bo), 0.0f);
            ull aiB = pack2(fmaf(xb, vi, bi), 0.0f);
            ull afB = pack2(fmaf(xb, vf, bf), 0.0f);
            ull agB = pack2(fmaf(xb, vg, bg), 0.0f);
            ull aoB = pack2(fmaf(xb, vo, bo), 0.0f);

            #pragma unroll
            for (int k = 0; k < 8; ++k) {
                const ulonglong2 ha = ra[k];     // LDS.128 broadcast
                const ulonglong2 hb = rb[k];
                fma2(aiA, wi[2 * k],     ha.x);
                fma2(aiB, wi[2 * k],     hb.x);
                fma2(afA, wf[2 * k],     ha.x);
                fma2(afB, wf[2 * k],     hb.x);
                fma2(agA, wg[2 * k],     ha.x);
                fma2(agB, wg[2 * k],     hb.x);
                fma2(aoA, wo[2 * k],     ha.x);
                fma2(aoB, wo[2 * k],     hb.x);
                fma2(aiA, wi[2 * k + 1], ha.y);
                fma2(aiB, wi[2 * k + 1], hb.y);
                fma2(afA, wf[2 * k + 1], ha.y);
                fma2(afB, wf[2 * k + 1], hb.y);
                fma2(agA, wg[2 * k + 1], ha.y);
                fma2(agB, wg[2 * k + 1], hb.y);
                fma2(aoA, wo[2 * k + 1], ha.y);
                fma2(aoB, wo[2 * k + 1], hb.y);
            }

            // two independent activation/update chains
            const float IA = sigm(hsum2(aiA));
            const float IB = sigm(hsum2(aiB));
            const float FA = sigm(hsum2(afA));
            const float FB = sigm(hsum2(afB));
            const float GA = tanhx(hsum2(agA));
            const float GB = tanhx(hsum2(agB));
            const float OA = sigm(hsum2(aoA));
            const float OB = sigm(hsum2(aoB));
            cA = fmaf(FA, cA, IA * GA);
            cB = fmaf(FB, cB, IB * GB);
            hA = OA * tanhx(cA);
            hB = OB * tanhx(cB);

            ((float*)hbA[p ^ 1])[lane] = hA;
            ((float*)hbB[p ^ 1])[lane] = hB;
            __syncwarp();
        }
    }

    // decoder input projection for both rows: pg = sum_j dWih[g][j]*h[j]
    float pA0 = hA * dWih[lane];
    float pA1 = hA * dWih[32 + lane];
    float pA2 = hA * dWih[64 + lane];
    float pA3 = hA * dWih[96 + lane];
    float pB0 = hB * dWih[lane];
    float pB1 = hB * dWih[32 + lane];
    float pB2 = hB * dWih[64 + lane];
    float pB3 = hB * dWih[96 + lane];
    #pragma unroll
    for (int m = 16; m > 0; m >>= 1) {
        pA0 += __shfl_xor_sync(0xffffffffu, pA0, m);
        pA1 += __shfl_xor_sync(0xffffffffu, pA1, m);
        pA2 += __shfl_xor_sync(0xffffffffu, pA2, m);
        pA3 += __shfl_xor_sync(0xffffffffu, pA3, m);
        pB0 += __shfl_xor_sync(0xffffffffu, pB0, m);
        pB1 += __shfl_xor_sync(0xffffffffu, pB1, m);
        pB2 += __shfl_xor_sync(0xffffffffu, pB2, m);
        pB3 += __shfl_xor_sync(0xffffffffu, pB3, m);
    }
    if (lane == 0) {
        g_pre[0][rA] = pA0 + dBih[0] + dBhh[0];
        g_pre[1][rA] = pA1 + dBih[1] + dBhh[1];
        g_pre[2][rA] = pA2 + dBih[2] + dBhh[2];
        g_pre[3][rA] = pA3 + dBih[3] + dBhh[3];
        g_pre[0][rB] = pB0 + dBih[0] + dBhh[0];
        g_pre[1][rB] = pB1 + dBih[1] + dBhh[1];
        g_pre[2][rB] = pB2 + dBih[2] + dBhh[2];
        g_pre[3][rB] = pB3 + dBih[3] + dBhh[3];
    }
}

// ============================================================================
// Decoder: one batch row per THREAD (H=1 scalar recurrence). 8192 threads.
// ============================================================================
__global__ void __launch_bounds__(32) dec_kernel(
    const float* __restrict__ dWhh,   // [4]
    float* __restrict__ out)          // [B, T]
{
    const int r = blockIdx.x * 32 + threadIdx.x;

    const float pre0 = g_pre[0][r];
    const float pre1 = g_pre[1][r];
    const float pre2 = g_pre[2][r];
    const float pre3 = g_pre[3][r];
    const float q0 = dWhh[0], q1 = dWhh[1], q2 = dWhh[2], q3 = dWhh[3];

    float hd = 0.0f, cd = 0.0f;
    float* orow = out + (size_t)r * SEQT;

    #pragma unroll 1
    for (int t = 0; t < SEQT; t += 4) {
        float v[4];
        #pragma unroll
        for (int s = 0; s < 4; ++s) {
            const float I = sigm(fmaf(hd, q0, pre0));
            const float F = sigm(fmaf(hd, q1, pre1));
            const float G = tanhx(fmaf(hd, q2, pre2));
            const float O = sigm(fmaf(hd, q3, pre3));
            cd = fmaf(F, cd, I * G);
            hd = O * tanhx(cd);
            v[s] = hd;
        }
        *(float4*)(orow + t) = make_float4(v[0], v[1], v[2], v[3]);
    }
}

extern "C" void kernel_launch(void* const* d_in, const int* in_sizes, int n_in,
                              void* d_out, int out_size) {
    (void)in_sizes; (void)n_in; (void)out_size;
    enc_kernel<<<BATCH / 2, 32>>>(
        (const float*)d_in[0],
        (const float*)d_in[1], (const float*)d_in[2],
        (const float*)d_in[3], (const float*)d_in[4],
        (const float*)d_in[5],
        (const float*)d_in[7], (const float*)d_in[8]);
    dec_kernel<<<BATCH / 32, 32>>>(
        (const float*)d_in[6],
        (float*)d_out);
}